// round 1
// baseline (speedup 1.0000x reference)
#include <cuda_runtime.h>
#include <cuda_bf16.h>
#include <math.h>

// ---------------------------------------------------------------------------
// Problem constants
// ---------------------------------------------------------------------------
#define B  8
#define H  512
#define W  512
#define PLANE (H*W)            // 262144 = 2^18
#define NPIX (B*PLANE)         // 2097152

// ---------------------------------------------------------------------------
// Scratch (device globals; allocation-free kernel_launch)
// ---------------------------------------------------------------------------
__device__ float g_f1[(size_t)B*32*PLANE];   // conv1 out
__device__ float g_f2[(size_t)B*16*PLANE];   // conv2 out
__device__ float g_f [(size_t)B* 8*PLANE];   // conv3 out (features)
__device__ float g_maps[(size_t)3*NPIX];     // per-scale std maps (post-pow)
__device__ float g_fused[(size_t)NPIX];      // fused map
__device__ unsigned g_h1[8192];
__device__ unsigned g_h2[4*8192];
__device__ unsigned g_h3[4*64];
__device__ float2 g_stats[32];               // per (b,c) sum/sumsq of x
__device__ float g_thr[64];                  // lower[32], diff[32]

struct QState {
    unsigned pref1[4];
    unsigned rem[4];
    unsigned pref2[4];
    float q25, q75, iqr;
};
__device__ QState g_qs;

// ---------------------------------------------------------------------------
// Zero transient accumulators (runs first every replay)
// ---------------------------------------------------------------------------
__global__ void zero_k() {
    int i = blockIdx.x * blockDim.x + threadIdx.x;
    int n = gridDim.x * blockDim.x;
    for (int j = i; j < 8192; j += n)    g_h1[j] = 0u;
    for (int j = i; j < 4*8192; j += n)  g_h2[j] = 0u;
    for (int j = i; j < 4*64; j += n)    g_h3[j] = 0u;
    for (int j = i; j < 32; j += n)      g_stats[j] = make_float2(0.f, 0.f);
}

// ---------------------------------------------------------------------------
// Direct 3x3 conv, zero pad 1, optional leaky-relu(0.2)
// Tile: 32 cols x (8*PIX) rows, 256 threads, each thread PIX pixels x COUT chans
// ---------------------------------------------------------------------------
template<int CIN, int COUT, int CCH, int PIX, bool LEAKY>
__global__ __launch_bounds__(256)
void conv3x3_k(const float* __restrict__ in, const float* __restrict__ wt,
               const float* __restrict__ bias, float* __restrict__ out) {
    constexpr int TW = 32;
    constexpr int TH = 8 * PIX;
    __shared__ float w_s[COUT * CIN * 9];
    __shared__ float tile[CCH][TH + 2][TW + 3];   // +3: pad for bank spread

    const int tid = threadIdx.x;
    const int tx = tid & 31, ty = tid >> 5;
    const int x0 = blockIdx.x * TW;
    const int y0 = blockIdx.y * TH;
    const int b  = blockIdx.z;

    for (int i = tid; i < COUT * CIN * 9; i += 256) w_s[i] = wt[i];

    float acc[PIX][COUT];
#pragma unroll
    for (int q = 0; q < PIX; q++)
#pragma unroll
        for (int co = 0; co < COUT; co++) acc[q][co] = 0.f;

#pragma unroll 1
    for (int ch0 = 0; ch0 < CIN; ch0 += CCH) {
        __syncthreads();
        const int NEL = CCH * (TH + 2) * (TW + 2);
        for (int i = tid; i < NEL; i += 256) {
            int c   = i / ((TH + 2) * (TW + 2));
            int rem = i % ((TH + 2) * (TW + 2));
            int yy  = rem / (TW + 2);
            int xx  = rem % (TW + 2);
            int gy = y0 + yy - 1, gx = x0 + xx - 1;
            float v = 0.f;
            if (gy >= 0 && gy < H && gx >= 0 && gx < W)
                v = in[(((size_t)b * CIN + ch0 + c) * H + gy) * W + gx];
            tile[c][yy][xx] = v;
        }
        __syncthreads();
#pragma unroll 1
        for (int ci = 0; ci < CCH; ci++) {
            const float* wrow = &w_s[(ch0 + ci) * 9];
#pragma unroll
            for (int kh = 0; kh < 3; kh++) {
#pragma unroll
                for (int kw = 0; kw < 3; kw++) {
                    float xv[PIX];
#pragma unroll
                    for (int q = 0; q < PIX; q++)
                        xv[q] = tile[ci][ty + 8 * q + kh][tx + kw];
#pragma unroll
                    for (int co = 0; co < COUT; co++) {
                        float wv = wrow[co * CIN * 9 + kh * 3 + kw];
#pragma unroll
                        for (int q = 0; q < PIX; q++)
                            acc[q][co] = fmaf(xv[q], wv, acc[q][co]);
                    }
                }
            }
        }
    }

#pragma unroll
    for (int co = 0; co < COUT; co++) {
        float bv = bias[co];
#pragma unroll
        for (int q = 0; q < PIX; q++) {
            float v = acc[q][co] + bv;
            if (LEAKY) v = (v >= 0.f) ? v : 0.2f * v;
            out[(((size_t)b * COUT + co) * H + (y0 + ty + 8 * q)) * W + (x0 + tx)] = v;
        }
    }
}

// ---------------------------------------------------------------------------
// Multi-scale box variance -> std maps with reflect padding.
// One block = (row strip, scale, batch). Thread = column.
// Incremental vertical column sums + per-row block prefix scan (float2: f, f^2).
// ---------------------------------------------------------------------------
__device__ __forceinline__ int refl(int i) {
    return i < 0 ? -i : (i > H - 1 ? 2 * (H - 1) - i : i);
}

__global__ __launch_bounds__(512)
void boxstd_k() {
    constexpr int ROWS = 64;
    __shared__ float csA[8][W];
    __shared__ float csB[8][W];
    __shared__ float2 pref[W + 1];
    __shared__ float2 wsum[16];

    const int j     = threadIdx.x;
    const int lane  = j & 31;
    const int wid   = j >> 5;
    const int strip = blockIdx.x;
    const int scale = blockIdx.y;
    const int b     = blockIdx.z;

    const int K = (scale == 0) ? 11 : (scale == 1) ? 25 : 49;
    const int P = K >> 1;
    const float inv = 1.f / (float)(K * K);
    const int r0 = strip * ROWS;

    // init column sums over rows [r0-P, r0+P] (reflect)
    for (int c = 0; c < 8; c++) {
        const float* fp = g_f + ((size_t)(b * 8 + c)) * PLANE;
        float s = 0.f, s2 = 0.f;
        for (int i = r0 - P; i <= r0 + P; i++) {
            float v = fp[refl(i) * W + j];
            s += v;
            s2 = fmaf(v, v, s2);
        }
        csA[c][j] = s;
        csB[c][j] = s2;
    }

    for (int r = r0; r < r0 + ROWS; r++) {
        if (r > r0) {
            int ra = refl(r + P), rs = refl(r - 1 - P);
            for (int c = 0; c < 8; c++) {
                const float* fp = g_f + ((size_t)(b * 8 + c)) * PLANE;
                float va = fp[ra * W + j], vs = fp[rs * W + j];
                csA[c][j] += va - vs;
                csB[c][j] += va * va - vs * vs;
            }
        }
        float rowacc = 0.f;
        for (int c = 0; c < 8; c++) {
            float2 sc = make_float2(csA[c][j], csB[c][j]);
            // warp inclusive scan
#pragma unroll
            for (int d = 1; d < 32; d <<= 1) {
                float ax = __shfl_up_sync(0xffffffffu, sc.x, d);
                float ay = __shfl_up_sync(0xffffffffu, sc.y, d);
                if (lane >= d) { sc.x += ax; sc.y += ay; }
            }
            if (lane == 31) wsum[wid] = sc;
            __syncthreads();
            if (wid == 0) {
                float2 t = (lane < 16) ? wsum[lane] : make_float2(0.f, 0.f);
#pragma unroll
                for (int d = 1; d < 16; d <<= 1) {
                    float ax = __shfl_up_sync(0xffffffffu, t.x, d);
                    float ay = __shfl_up_sync(0xffffffffu, t.y, d);
                    if (lane >= d) { t.x += ax; t.y += ay; }
                }
                if (lane < 16) wsum[lane] = t;
            }
            __syncthreads();
            if (wid > 0) { sc.x += wsum[wid - 1].x; sc.y += wsum[wid - 1].y; }
            pref[j + 1] = sc;
            if (j == 0) pref[0] = make_float2(0.f, 0.f);
            __syncthreads();

            const int lo = j - P, hi = j + P;
            const int loC = max(lo, 0), hiC = min(hi, W - 1);
            float2 S;
            S.x = pref[hiC + 1].x - pref[loC].x;
            S.y = pref[hiC + 1].y - pref[loC].y;
            if (lo < 0) {            // reflect cols 1..(-lo)
                S.x += pref[-lo + 1].x - pref[1].x;
                S.y += pref[-lo + 1].y - pref[1].y;
            }
            if (hi > W - 1) {        // reflect cols (2(W-1)-hi)..(W-2)
                S.x += pref[W - 1].x - pref[2 * (W - 1) - hi].x;
                S.y += pref[W - 1].y - pref[2 * (W - 1) - hi].y;
            }
            float m  = S.x * inv;
            float m2 = S.y * inv;
            float var = fmaxf(m2 - m * m, 1e-6f);
            rowacc += sqrtf(var);
            __syncthreads();
        }
        g_maps[(size_t)scale * NPIX + ((size_t)b * H + r) * W + j] =
            powf(rowacc * 0.125f, 0.8f);
    }
}

// ---------------------------------------------------------------------------
// Fusion (1x1 conv over 3 maps + relu) + level-1 histogram (bits >> 19)
// ---------------------------------------------------------------------------
__global__ void fuse_hist1_k(const float* __restrict__ fw, const float* __restrict__ fb) {
    __shared__ unsigned h[8192];
    for (int i = threadIdx.x; i < 8192; i += blockDim.x) h[i] = 0u;
    __syncthreads();
    const float w0 = fw[0], w1 = fw[1], w2 = fw[2], b0 = fb[0];
    const size_t N = NPIX;
    for (size_t i = (size_t)blockIdx.x * blockDim.x + threadIdx.x; i < N;
         i += (size_t)gridDim.x * blockDim.x) {
        float v = w0 * g_maps[i] + w1 * g_maps[i + N] + w2 * g_maps[i + 2 * N] + b0;
        v = fmaxf(v, 0.f);
        g_fused[i] = v;
        atomicAdd(&h[__float_as_uint(v) >> 19], 1u);
    }
    __syncthreads();
    for (int i = threadIdx.x; i < 8192; i += blockDim.x)
        if (h[i]) atomicAdd(&g_h1[i], h[i]);
}

// ---------------------------------------------------------------------------
// Rank finder over a histogram (cooperative, 256 threads)
// ---------------------------------------------------------------------------
__device__ void findRank(const unsigned* __restrict__ hist, int nbins, unsigned rank,
                         unsigned* sbin, unsigned* srem,
                         unsigned* sp, unsigned* sb) {
    __syncthreads();
    const int tid = threadIdx.x;
    const int chunk = nbins / 256;
    unsigned loc = 0;
    for (int i = 0; i < chunk; i++) loc += hist[tid * chunk + i];
    sp[tid] = loc;
    __syncthreads();
    if (tid == 0) {
        unsigned c = 0;
        for (int i = 0; i < 256; i++) { sb[i] = c; c += sp[i]; }
    }
    __syncthreads();
    unsigned cum = sb[tid];
    for (int i = 0; i < chunk; i++) {
        unsigned cnt = hist[tid * chunk + i];
        if (rank >= cum && rank < cum + cnt) { *sbin = tid * chunk + i; *srem = rank - cum; }
        cum += cnt;
    }
    __syncthreads();
}

__global__ void scan1_k() {
    __shared__ unsigned sp[256], sb[256];
    __shared__ unsigned rbin, rrem;
    const unsigned ranks[4] = {524287u, 524288u, 1572863u, 1572864u};
    for (int r = 0; r < 4; r++) {
        findRank(g_h1, 8192, ranks[r], &rbin, &rrem, sp, sb);
        if (threadIdx.x == 0) { g_qs.pref1[r] = rbin; g_qs.rem[r] = rrem; }
        __syncthreads();
    }
}

__global__ void hist2_k() {
    const int r = blockIdx.y;
    const unsigned pref = g_qs.pref1[r];
    __shared__ unsigned h[8192];
    for (int i = threadIdx.x; i < 8192; i += blockDim.x) h[i] = 0u;
    __syncthreads();
    for (size_t i = (size_t)blockIdx.x * blockDim.x + threadIdx.x; i < (size_t)NPIX;
         i += (size_t)gridDim.x * blockDim.x) {
        unsigned bits = __float_as_uint(g_fused[i]);
        if ((bits >> 19) == pref) atomicAdd(&h[(bits >> 6) & 8191u], 1u);
    }
    __syncthreads();
    for (int i = threadIdx.x; i < 8192; i += blockDim.x)
        if (h[i]) atomicAdd(&g_h2[r * 8192 + i], h[i]);
}

__global__ void scan2_k() {
    __shared__ unsigned sp[256], sb[256];
    __shared__ unsigned rbin, rrem;
    for (int r = 0; r < 4; r++) {
        unsigned rank = g_qs.rem[r];
        findRank(g_h2 + r * 8192, 8192, rank, &rbin, &rrem, sp, sb);
        if (threadIdx.x == 0) {
            g_qs.pref2[r] = (g_qs.pref1[r] << 13) | rbin;
            g_qs.rem[r]   = rrem;
        }
        __syncthreads();
    }
}

__global__ void hist3_k() {
    const int r = blockIdx.y;
    const unsigned pref = g_qs.pref2[r];
    __shared__ unsigned h[64];
    if (threadIdx.x < 64) h[threadIdx.x] = 0u;
    __syncthreads();
    for (size_t i = (size_t)blockIdx.x * blockDim.x + threadIdx.x; i < (size_t)NPIX;
         i += (size_t)gridDim.x * blockDim.x) {
        unsigned bits = __float_as_uint(g_fused[i]);
        if ((bits >> 6) == pref) atomicAdd(&h[bits & 63u], 1u);
    }
    __syncthreads();
    if (threadIdx.x < 64 && h[threadIdx.x]) atomicAdd(&g_h3[r * 64 + threadIdx.x], h[threadIdx.x]);
}

__global__ void scan3_k() {
    __shared__ float sv[4];
    const int r = threadIdx.x;
    if (r < 4) {
        unsigned rank = g_qs.rem[r];
        unsigned cum = 0, bin = 0;
        for (int i = 0; i < 64; i++) {
            unsigned c = g_h3[r * 64 + i];
            if (rank >= cum && rank < cum + c) bin = (unsigned)i;
            cum += c;
        }
        sv[r] = __uint_as_float((g_qs.pref2[r] << 6) | bin);
    }
    __syncthreads();
    if (r == 0) {
        float q25 = sv[0] + 0.75f * (sv[1] - sv[0]);
        float q75 = sv[2] + 0.25f * (sv[3] - sv[2]);
        float iqr = q75 - q25;
        if (iqr < 1e-5f) iqr = 0.05f;
        g_qs.q25 = q25; g_qs.q75 = q75; g_qs.iqr = iqr;
    }
}

// ---------------------------------------------------------------------------
// Per-(b,c) sum / sumsq of x
// ---------------------------------------------------------------------------
__global__ void xstats_k(const float* __restrict__ x) {
    const int bc = blockIdx.x;             // 0..31
    const int sl = blockIdx.y;             // 0..7
    const float* p = x + ((size_t)bc << 18) + (size_t)sl * 32768;
    float s = 0.f, s2 = 0.f;
    for (int i = threadIdx.x; i < 32768; i += 256) {
        float v = p[i];
        s += v;
        s2 = fmaf(v, v, s2);
    }
#pragma unroll
    for (int o = 16; o; o >>= 1) {
        s  += __shfl_xor_sync(0xffffffffu, s, o);
        s2 += __shfl_xor_sync(0xffffffffu, s2, o);
    }
    __shared__ float ss[8], ss2[8];
    int w = threadIdx.x >> 5, l = threadIdx.x & 31;
    if (l == 0) { ss[w] = s; ss2[w] = s2; }
    __syncthreads();
    if (threadIdx.x == 0) {
        float a = 0.f, a2 = 0.f;
        for (int i = 0; i < 8; i++) { a += ss[i]; a2 += ss2[i]; }
        atomicAdd(&g_stats[bc].x, a);
        atomicAdd(&g_stats[bc].y, a2);
    }
}

// ---------------------------------------------------------------------------
// Adaptive thresholds (1 warp)
// ---------------------------------------------------------------------------
__global__ void thr_k(const float* __restrict__ chw) {
    const int t = threadIdx.x;       // bc = b*4 + c
    const int c = t & 3;
    float w0 = chw[0], w1 = chw[1], w2 = chw[2], w3 = chw[3];
    float mx = fmaxf(fmaxf(w0, w1), fmaxf(w2, w3));
    float e0 = expf(w0 - mx), e1 = expf(w1 - mx), e2 = expf(w2 - mx), e3 = expf(w3 - mx);
    float se = e0 + e1 + e2 + e3;
    float cw = ((c == 0) ? e0 : (c == 1) ? e1 : (c == 2) ? e2 : e3) / se;

    float2 st = g_stats[t];
    const float N = (float)PLANE;
    float var = (st.y - st.x * st.x / N) / (N - 1.f);
    float gstd = sqrtf(fmaxf(var, 0.f));

    float q25 = g_qs.q25, q75 = g_qs.q75, iqr = g_qs.iqr;
    float lower = q25 - 0.5f * iqr;
    float upper = q75 + 0.5f * iqr;
    float gf = fminf(fmaxf(gstd * 5.f, 0.5f), 2.f);
    lower *= gf; upper *= gf;
    float cf = fminf(fmaxf(cw * gstd * 2.f, 0.8f), 1.2f);
    lower *= cf; upper *= cf;

    float d = fabsf(upper - lower);
#pragma unroll
    for (int o = 16; o; o >>= 1) d = fminf(d, __shfl_xor_sync(0xffffffffu, d, o));
    if (d < 1e-5f) {
        float mt = 0.5f * (upper + lower);
        lower = mt - 0.05f;
        upper = mt + 0.05f;
    }
    g_thr[t]      = lower;
    g_thr[32 + t] = fmaxf(upper - lower, 1e-5f);
}

// ---------------------------------------------------------------------------
// Final texture mask: mean over 4 channels of sigmoid(6*clip(...)-3)
// ---------------------------------------------------------------------------
__global__ void mask_k(float* __restrict__ out) {
    for (size_t i = (size_t)blockIdx.x * blockDim.x + threadIdx.x; i < (size_t)NPIX;
         i += (size_t)gridDim.x * blockDim.x) {
        int b = (int)(i >> 18);
        float v = g_fused[i];
        float acc = 0.f;
#pragma unroll
        for (int c = 0; c < 4; c++) {
            float lo  = g_thr[b * 4 + c];
            float dif = g_thr[32 + b * 4 + c];
            float nrm = fminf(fmaxf((v - lo) / dif, 0.f), 1.f);
            acc += 1.f / (1.f + expf(3.f - 6.f * nrm));
        }
        out[i] = 0.25f * acc;
    }
}

// ---------------------------------------------------------------------------
// Launch
// ---------------------------------------------------------------------------
extern "C" void kernel_launch(void* const* d_in, const int* in_sizes, int n_in,
                              void* d_out, int out_size) {
    const float* x        = (const float*)d_in[0];
    const float* conv1_w  = (const float*)d_in[1];
    const float* conv1_b  = (const float*)d_in[2];
    const float* conv2_w  = (const float*)d_in[3];
    const float* conv2_b  = (const float*)d_in[4];
    const float* conv3_w  = (const float*)d_in[5];
    const float* conv3_b  = (const float*)d_in[6];
    const float* fusion_w = (const float*)d_in[7];
    const float* fusion_b = (const float*)d_in[8];
    const float* chw      = (const float*)d_in[9];
    float* out = (float*)d_out;

    float* f1; cudaGetSymbolAddress((void**)&f1, g_f1);
    float* f2; cudaGetSymbolAddress((void**)&f2, g_f2);
    float* f ; cudaGetSymbolAddress((void**)&f , g_f);

    zero_k<<<64, 256>>>();

    // conv1: 4 -> 32, leaky
    conv3x3_k<4, 32, 4, 2, true><<<dim3(W/32, H/16, B), 256>>>(x, conv1_w, conv1_b, f1);
    // conv2: 32 -> 16, leaky
    conv3x3_k<32, 16, 4, 4, true><<<dim3(W/32, H/32, B), 256>>>(f1, conv2_w, conv2_b, f2);
    // conv3: 16 -> 8
    conv3x3_k<16, 8, 8, 4, false><<<dim3(W/32, H/32, B), 256>>>(f2, conv3_w, conv3_b, f);

    // multi-scale std maps (scales in blockIdx.y)
    boxstd_k<<<dim3(H/64, 3, B), 512>>>();

    // fusion + quantile histograms
    fuse_hist1_k<<<192, 256>>>(fusion_w, fusion_b);
    scan1_k<<<1, 256>>>();
    hist2_k<<<dim3(64, 4), 256>>>();
    scan2_k<<<1, 256>>>();
    hist3_k<<<dim3(64, 4), 256>>>();
    scan3_k<<<1, 32>>>();

    // x statistics + thresholds
    xstats_k<<<dim3(32, 8), 256>>>(x);
    thr_k<<<1, 32>>>(chw);

    // final mask
    mask_k<<<1024, 256>>>(out);
}

// round 2
// speedup vs baseline: 1.1477x; 1.1477x over previous
#include <cuda_runtime.h>
#include <cuda_bf16.h>
#include <math.h>
#include <stdint.h>

// ---------------------------------------------------------------------------
// Problem constants
// ---------------------------------------------------------------------------
#define B  8
#define H  512
#define W  512
#define PLANE (H*W)            // 262144 = 2^18
#define NPIX (B*PLANE)         // 2097152

// ---------------------------------------------------------------------------
// Scratch (device globals; allocation-free kernel_launch)
// ---------------------------------------------------------------------------
__device__ float g_f1[(size_t)B*32*PLANE];   // conv1 out
__device__ float g_f2[(size_t)B*16*PLANE];   // conv2 out
__device__ float g_f [(size_t)B* 8*PLANE];   // conv3 out (features)
__device__ float g_maps[(size_t)3*NPIX];     // per-scale std maps (post-pow)
__device__ float g_fused[(size_t)NPIX];      // fused map
__device__ unsigned g_h1[8192];
__device__ unsigned g_h2[4*8192];
__device__ unsigned g_h3[4*64];
__device__ float2 g_stats[32];               // per (b,c) sum/sumsq of x
__device__ float g_thr[64];                  // lower[32], diff[32]

struct QState {
    unsigned pref1[4];
    unsigned rem[4];
    unsigned pref2[4];
    float q25, q75, iqr;
};
__device__ QState g_qs;

// ---------------------------------------------------------------------------
// Zero transient accumulators (runs first every replay)
// ---------------------------------------------------------------------------
__global__ void zero_k() {
    int i = blockIdx.x * blockDim.x + threadIdx.x;
    int n = gridDim.x * blockDim.x;
    for (int j = i; j < 8192; j += n)    g_h1[j] = 0u;
    for (int j = i; j < 4*8192; j += n)  g_h2[j] = 0u;
    for (int j = i; j < 4*64; j += n)    g_h3[j] = 0u;
    for (int j = i; j < 32; j += n)      g_stats[j] = make_float2(0.f, 0.f);
}

// ---------------------------------------------------------------------------
// TF32 helpers
// ---------------------------------------------------------------------------
__device__ __forceinline__ uint32_t f2tf(float f) {
    uint32_t r;
    asm("cvt.rna.tf32.f32 %0, %1;" : "=r"(r) : "f"(f));
    return r;
}

__device__ __forceinline__ void mma8(float* d, const uint32_t* a, const uint32_t* b) {
    asm("mma.sync.aligned.m16n8k8.row.col.f32.tf32.tf32.f32 "
        "{%0,%1,%2,%3}, {%4,%5,%6,%7}, {%8,%9}, {%0,%1,%2,%3};"
        : "+f"(d[0]), "+f"(d[1]), "+f"(d[2]), "+f"(d[3])
        : "r"(a[0]), "r"(a[1]), "r"(a[2]), "r"(a[3]), "r"(b[0]), "r"(b[1]));
}

__device__ __forceinline__ void mma4(float* d, uint32_t a0, uint32_t a1, uint32_t b0) {
    asm("mma.sync.aligned.m16n8k4.row.col.f32.tf32.tf32.f32 "
        "{%0,%1,%2,%3}, {%4,%5}, {%6}, {%0,%1,%2,%3};"
        : "+f"(d[0]), "+f"(d[1]), "+f"(d[2]), "+f"(d[3])
        : "r"(a0), "r"(a1), "r"(b0));
}

// Split v into tf32 big + tf32 small (3xTF32 decomposition)
__device__ __forceinline__ void tf_split(float v, uint32_t& vb, uint32_t& vs) {
    vb = f2tf(v);
    float r = v - __uint_as_float(vb);
    vs = f2tf(r);
}

// ---------------------------------------------------------------------------
// conv1: CIN=4, COUT=32, k4 MMA. Tile 8 rows x 64 cols, 8 warps (1 row each).
// ---------------------------------------------------------------------------
__global__ __launch_bounds__(256, 2)
void conv1_mma_k(const float* __restrict__ in, const float* __restrict__ wt,
                 const float* __restrict__ bias, float* __restrict__ out) {
    constexpr int CIN = 4, COUT = 32, K9 = 36, COP = 33;
    extern __shared__ float smem[];
    float* ws_big   = smem;                 // [K9][COP]
    float* ws_small = smem + K9 * COP;
    float* tile     = smem + 2 * K9 * COP;  // [4][10][68]

    const int tid = threadIdx.x;
    const int wid = tid >> 5;
    const int lane = tid & 31;
    const int gid = lane >> 2;     // 0..7
    const int tig = lane & 3;      // 0..3
    const int x0 = blockIdx.x * 64;
    const int y0 = blockIdx.y * 8;
    const int b  = blockIdx.z;

    // stage split weights: ws[k][co], k = ci*9 + s
    for (int i = tid; i < K9 * COUT; i += 256) {
        int k = i / COUT, co = i % COUT;
        float w = wt[co * K9 + k];
        uint32_t wb, wsm;
        tf_split(w, wb, wsm);
        ws_big[k * COP + co]   = __uint_as_float(wb);
        ws_small[k * COP + co] = __uint_as_float(wsm);
    }
    // tile: 4ch x 10 x 66 (stride 68)
    for (int i = tid; i < 4 * 10 * 66; i += 256) {
        int c = i / 660, rem = i % 660;
        int yy = rem / 66, xx = rem % 66;
        int gy = y0 + yy - 1, gx = x0 + xx - 1;
        float v = 0.f;
        if (gy >= 0 && gy < H && gx >= 0 && gx < W)
            v = in[(((size_t)b * CIN + c) * H + gy) * W + gx];
        tile[c * 680 + yy * 68 + xx] = v;
    }
    __syncthreads();

    float acc[2][8][4];
#pragma unroll
    for (int m = 0; m < 2; m++)
#pragma unroll
        for (int g = 0; g < 8; g++)
#pragma unroll
            for (int q = 0; q < 4; q++) acc[m][g][q] = 0.f;

#pragma unroll
    for (int s = 0; s < 9; s++) {
        const int kh = s / 3, kw = s % 3;
        const int k = tig * 9 + s;
        uint32_t a0b = __float_as_uint(ws_big[k * COP + gid]);
        uint32_t a1b = __float_as_uint(ws_big[k * COP + gid + 8]);
        uint32_t a2b = __float_as_uint(ws_big[k * COP + 16 + gid]);
        uint32_t a3b = __float_as_uint(ws_big[k * COP + 16 + gid + 8]);
        uint32_t a0s = __float_as_uint(ws_small[k * COP + gid]);
        uint32_t a1s = __float_as_uint(ws_small[k * COP + gid + 8]);
        uint32_t a2s = __float_as_uint(ws_small[k * COP + 16 + gid]);
        uint32_t a3s = __float_as_uint(ws_small[k * COP + 16 + gid + 8]);
#pragma unroll
        for (int g = 0; g < 8; g++) {
            float v = tile[tig * 680 + (wid + kh) * 68 + g * 8 + gid + kw];
            uint32_t bb, bs;
            tf_split(v, bb, bs);
            mma4(acc[0][g], a0b, a1b, bb);
            mma4(acc[0][g], a0s, a1s, bb);
            mma4(acc[0][g], a0b, a1b, bs);
            mma4(acc[1][g], a2b, a3b, bb);
            mma4(acc[1][g], a2s, a3s, bb);
            mma4(acc[1][g], a2b, a3b, bs);
        }
    }

    const int gy = y0 + wid;
#pragma unroll
    for (int m = 0; m < 2; m++) {
        int co0 = m * 16 + gid;
        float b0 = bias[co0], b1 = bias[co0 + 8];
#pragma unroll
        for (int g = 0; g < 8; g++) {
            int gx = x0 + g * 8 + 2 * tig;
            float2 o0, o1;
            o0.x = acc[m][g][0] + b0; o0.y = acc[m][g][1] + b0;
            o1.x = acc[m][g][2] + b1; o1.y = acc[m][g][3] + b1;
            o0.x = (o0.x >= 0.f) ? o0.x : 0.2f * o0.x;
            o0.y = (o0.y >= 0.f) ? o0.y : 0.2f * o0.y;
            o1.x = (o1.x >= 0.f) ? o1.x : 0.2f * o1.x;
            o1.y = (o1.y >= 0.f) ? o1.y : 0.2f * o1.y;
            *(float2*)&out[(((size_t)b * COUT + co0) * H + gy) * W + gx] = o0;
            *(float2*)&out[(((size_t)b * COUT + co0 + 8) * H + gy) * W + gx] = o1;
        }
    }
}

// ---------------------------------------------------------------------------
// conv2/conv3: k8 MMA, CIN multiple of 8. Tile 16 rows x 64 cols, 8 warps
// (2 rows each). 3xTF32 compensated.
// ---------------------------------------------------------------------------
template<int CIN, int COUT, bool LEAKY>
__global__ __launch_bounds__(256, 2)
void convB_mma_k(const float* __restrict__ in, const float* __restrict__ wt,
                 const float* __restrict__ bias, float* __restrict__ out) {
    constexpr int K9 = CIN * 9;
    constexpr int COP = COUT + 1;
    extern __shared__ float smem[];
    float* ws_big   = smem;                 // [K9][COP]
    float* ws_small = smem + K9 * COP;
    float* tile     = smem + 2 * K9 * COP;  // [8][18][68]

    const int tid = threadIdx.x;
    const int wid = tid >> 5;
    const int lane = tid & 31;
    const int gid = lane >> 2;
    const int tig = lane & 3;
    const int x0 = blockIdx.x * 64;
    const int y0 = blockIdx.y * 16;
    const int b  = blockIdx.z;

    for (int i = tid; i < K9 * COUT; i += 256) {
        int k = i / COUT, co = i % COUT;
        float w = wt[co * K9 + k];
        uint32_t wb, wsm;
        tf_split(w, wb, wsm);
        ws_big[k * COP + co]   = __uint_as_float(wb);
        ws_small[k * COP + co] = __uint_as_float(wsm);
    }

    float acc[16][4];
#pragma unroll
    for (int g = 0; g < 16; g++)
#pragma unroll
        for (int q = 0; q < 4; q++) acc[g][q] = 0.f;

#pragma unroll 1
    for (int ch = 0; ch < CIN / 8; ch++) {
        __syncthreads();
        // tile: 8ch x 18 x 66 (stride 68)
        for (int i = tid; i < 8 * 18 * 66; i += 256) {
            int c = i / (18 * 66), rem = i % (18 * 66);
            int yy = rem / 66, xx = rem % 66;
            int gy = y0 + yy - 1, gx = x0 + xx - 1;
            float v = 0.f;
            if (gy >= 0 && gy < H && gx >= 0 && gx < W)
                v = in[(((size_t)b * CIN + ch * 8 + c) * H + gy) * W + gx];
            tile[c * 1224 + yy * 68 + xx] = v;
        }
        __syncthreads();

#pragma unroll
        for (int s = 0; s < 9; s++) {
            const int kh = s / 3, kw = s % 3;
            const int k0 = (ch * 8 + tig) * 9 + s;
            const int k1 = k0 + 36;          // +4 channels * 9
            uint32_t ab[4], as[4];
            ab[0] = __float_as_uint(ws_big[k0 * COP + gid]);
            ab[2] = __float_as_uint(ws_big[k1 * COP + gid]);
            as[0] = __float_as_uint(ws_small[k0 * COP + gid]);
            as[2] = __float_as_uint(ws_small[k1 * COP + gid]);
            if (COUT > 8) {
                ab[1] = __float_as_uint(ws_big[k0 * COP + gid + 8]);
                ab[3] = __float_as_uint(ws_big[k1 * COP + gid + 8]);
                as[1] = __float_as_uint(ws_small[k0 * COP + gid + 8]);
                as[3] = __float_as_uint(ws_small[k1 * COP + gid + 8]);
            } else {
                ab[1] = ab[3] = as[1] = as[3] = 0u;
            }
#pragma unroll
            for (int g = 0; g < 16; g++) {
                int ry = 2 * wid + (g >> 3);
                int cx = (g & 7) * 8 + gid;
                float v0 = tile[tig * 1224 + (ry + kh) * 68 + cx + kw];
                float v1 = tile[(tig + 4) * 1224 + (ry + kh) * 68 + cx + kw];
                uint32_t bb[2], bs[2];
                tf_split(v0, bb[0], bs[0]);
                tf_split(v1, bb[1], bs[1]);
                mma8(acc[g], ab, bb);
                mma8(acc[g], as, bb);
                mma8(acc[g], ab, bs);
            }
        }
    }

    float b0 = bias[gid];
    float b1 = (COUT > 8) ? bias[gid + 8] : 0.f;
#pragma unroll
    for (int g = 0; g < 16; g++) {
        int gy = y0 + 2 * wid + (g >> 3);
        int gx = x0 + (g & 7) * 8 + 2 * tig;
        float2 o0;
        o0.x = acc[g][0] + b0; o0.y = acc[g][1] + b0;
        if (LEAKY) {
            o0.x = (o0.x >= 0.f) ? o0.x : 0.2f * o0.x;
            o0.y = (o0.y >= 0.f) ? o0.y : 0.2f * o0.y;
        }
        *(float2*)&out[(((size_t)b * COUT + gid) * H + gy) * W + gx] = o0;
        if (COUT > 8) {
            float2 o1;
            o1.x = acc[g][2] + b1; o1.y = acc[g][3] + b1;
            if (LEAKY) {
                o1.x = (o1.x >= 0.f) ? o1.x : 0.2f * o1.x;
                o1.y = (o1.y >= 0.f) ? o1.y : 0.2f * o1.y;
            }
            *(float2*)&out[(((size_t)b * COUT + gid + 8) * H + gy) * W + gx] = o1;
        }
    }
}

// ---------------------------------------------------------------------------
// Multi-scale box variance -> std maps with reflect padding.
// ---------------------------------------------------------------------------
__device__ __forceinline__ int refl(int i) {
    return i < 0 ? -i : (i > H - 1 ? 2 * (H - 1) - i : i);
}

__global__ __launch_bounds__(512)
void boxstd_k() {
    constexpr int ROWS = 64;
    __shared__ float csA[8][W];
    __shared__ float csB[8][W];
    __shared__ float2 pref[W + 1];
    __shared__ float2 wsum[16];

    const int j     = threadIdx.x;
    const int lane  = j & 31;
    const int wid   = j >> 5;
    const int strip = blockIdx.x;
    const int scale = blockIdx.y;
    const int b     = blockIdx.z;

    const int K = (scale == 0) ? 11 : (scale == 1) ? 25 : 49;
    const int P = K >> 1;
    const float inv = 1.f / (float)(K * K);
    const int r0 = strip * ROWS;

    for (int c = 0; c < 8; c++) {
        const float* fp = g_f + ((size_t)(b * 8 + c)) * PLANE;
        float s = 0.f, s2 = 0.f;
        for (int i = r0 - P; i <= r0 + P; i++) {
            float v = fp[refl(i) * W + j];
            s += v;
            s2 = fmaf(v, v, s2);
        }
        csA[c][j] = s;
        csB[c][j] = s2;
    }

    for (int r = r0; r < r0 + ROWS; r++) {
        if (r > r0) {
            int ra = refl(r + P), rs = refl(r - 1 - P);
            for (int c = 0; c < 8; c++) {
                const float* fp = g_f + ((size_t)(b * 8 + c)) * PLANE;
                float va = fp[ra * W + j], vs = fp[rs * W + j];
                csA[c][j] += va - vs;
                csB[c][j] += va * va - vs * vs;
            }
        }
        float rowacc = 0.f;
        for (int c = 0; c < 8; c++) {
            float2 sc = make_float2(csA[c][j], csB[c][j]);
#pragma unroll
            for (int d = 1; d < 32; d <<= 1) {
                float ax = __shfl_up_sync(0xffffffffu, sc.x, d);
                float ay = __shfl_up_sync(0xffffffffu, sc.y, d);
                if (lane >= d) { sc.x += ax; sc.y += ay; }
            }
            if (lane == 31) wsum[wid] = sc;
            __syncthreads();
            if (wid == 0) {
                float2 t = (lane < 16) ? wsum[lane] : make_float2(0.f, 0.f);
#pragma unroll
                for (int d = 1; d < 16; d <<= 1) {
                    float ax = __shfl_up_sync(0xffffffffu, t.x, d);
                    float ay = __shfl_up_sync(0xffffffffu, t.y, d);
                    if (lane >= d) { t.x += ax; t.y += ay; }
                }
                if (lane < 16) wsum[lane] = t;
            }
            __syncthreads();
            if (wid > 0) { sc.x += wsum[wid - 1].x; sc.y += wsum[wid - 1].y; }
            pref[j + 1] = sc;
            if (j == 0) pref[0] = make_float2(0.f, 0.f);
            __syncthreads();

            const int lo = j - P, hi = j + P;
            const int loC = max(lo, 0), hiC = min(hi, W - 1);
            float2 S;
            S.x = pref[hiC + 1].x - pref[loC].x;
            S.y = pref[hiC + 1].y - pref[loC].y;
            if (lo < 0) {
                S.x += pref[-lo + 1].x - pref[1].x;
                S.y += pref[-lo + 1].y - pref[1].y;
            }
            if (hi > W - 1) {
                S.x += pref[W - 1].x - pref[2 * (W - 1) - hi].x;
                S.y += pref[W - 1].y - pref[2 * (W - 1) - hi].y;
            }
            float m  = S.x * inv;
            float m2 = S.y * inv;
            float var = fmaxf(m2 - m * m, 1e-6f);
            rowacc += sqrtf(var);
            __syncthreads();
        }
        g_maps[(size_t)scale * NPIX + ((size_t)b * H + r) * W + j] =
            powf(rowacc * 0.125f, 0.8f);
    }
}

// ---------------------------------------------------------------------------
// Fusion (1x1 conv over 3 maps + relu) + level-1 histogram (bits >> 19)
// ---------------------------------------------------------------------------
__global__ void fuse_hist1_k(const float* __restrict__ fw, const float* __restrict__ fb) {
    __shared__ unsigned h[8192];
    for (int i = threadIdx.x; i < 8192; i += blockDim.x) h[i] = 0u;
    __syncthreads();
    const float w0 = fw[0], w1 = fw[1], w2 = fw[2], b0 = fb[0];
    const size_t N = NPIX;
    for (size_t i = (size_t)blockIdx.x * blockDim.x + threadIdx.x; i < N;
         i += (size_t)gridDim.x * blockDim.x) {
        float v = w0 * g_maps[i] + w1 * g_maps[i + N] + w2 * g_maps[i + 2 * N] + b0;
        v = fmaxf(v, 0.f);
        g_fused[i] = v;
        atomicAdd(&h[__float_as_uint(v) >> 19], 1u);
    }
    __syncthreads();
    for (int i = threadIdx.x; i < 8192; i += blockDim.x)
        if (h[i]) atomicAdd(&g_h1[i], h[i]);
}

// ---------------------------------------------------------------------------
// Rank finder over a histogram (cooperative, 256 threads)
// ---------------------------------------------------------------------------
__device__ void findRank(const unsigned* __restrict__ hist, int nbins, unsigned rank,
                         unsigned* sbin, unsigned* srem,
                         unsigned* sp, unsigned* sb) {
    __syncthreads();
    const int tid = threadIdx.x;
    const int chunk = nbins / 256;
    unsigned loc = 0;
    for (int i = 0; i < chunk; i++) loc += hist[tid * chunk + i];
    sp[tid] = loc;
    __syncthreads();
    if (tid == 0) {
        unsigned c = 0;
        for (int i = 0; i < 256; i++) { sb[i] = c; c += sp[i]; }
    }
    __syncthreads();
    unsigned cum = sb[tid];
    for (int i = 0; i < chunk; i++) {
        unsigned cnt = hist[tid * chunk + i];
        if (rank >= cum && rank < cum + cnt) { *sbin = tid * chunk + i; *srem = rank - cum; }
        cum += cnt;
    }
    __syncthreads();
}

__global__ void scan1_k() {
    __shared__ unsigned sp[256], sb[256];
    __shared__ unsigned rbin, rrem;
    const unsigned ranks[4] = {524287u, 524288u, 1572863u, 1572864u};
    for (int r = 0; r < 4; r++) {
        findRank(g_h1, 8192, ranks[r], &rbin, &rrem, sp, sb);
        if (threadIdx.x == 0) { g_qs.pref1[r] = rbin; g_qs.rem[r] = rrem; }
        __syncthreads();
    }
}

__global__ void hist2_k() {
    const int r = blockIdx.y;
    const unsigned pref = g_qs.pref1[r];
    __shared__ unsigned h[8192];
    for (int i = threadIdx.x; i < 8192; i += blockDim.x) h[i] = 0u;
    __syncthreads();
    for (size_t i = (size_t)blockIdx.x * blockDim.x + threadIdx.x; i < (size_t)NPIX;
         i += (size_t)gridDim.x * blockDim.x) {
        unsigned bits = __float_as_uint(g_fused[i]);
        if ((bits >> 19) == pref) atomicAdd(&h[(bits >> 6) & 8191u], 1u);
    }
    __syncthreads();
    for (int i = threadIdx.x; i < 8192; i += blockDim.x)
        if (h[i]) atomicAdd(&g_h2[r * 8192 + i], h[i]);
}

__global__ void scan2_k() {
    __shared__ unsigned sp[256], sb[256];
    __shared__ unsigned rbin, rrem;
    for (int r = 0; r < 4; r++) {
        unsigned rank = g_qs.rem[r];
        findRank(g_h2 + r * 8192, 8192, rank, &rbin, &rrem, sp, sb);
        if (threadIdx.x == 0) {
            g_qs.pref2[r] = (g_qs.pref1[r] << 13) | rbin;
            g_qs.rem[r]   = rrem;
        }
        __syncthreads();
    }
}

__global__ void hist3_k() {
    const int r = blockIdx.y;
    const unsigned pref = g_qs.pref2[r];
    __shared__ unsigned h[64];
    if (threadIdx.x < 64) h[threadIdx.x] = 0u;
    __syncthreads();
    for (size_t i = (size_t)blockIdx.x * blockDim.x + threadIdx.x; i < (size_t)NPIX;
         i += (size_t)gridDim.x * blockDim.x) {
        unsigned bits = __float_as_uint(g_fused[i]);
        if ((bits >> 6) == pref) atomicAdd(&h[bits & 63u], 1u);
    }
    __syncthreads();
    if (threadIdx.x < 64 && h[threadIdx.x]) atomicAdd(&g_h3[r * 64 + threadIdx.x], h[threadIdx.x]);
}

__global__ void scan3_k() {
    __shared__ float sv[4];
    const int r = threadIdx.x;
    if (r < 4) {
        unsigned rank = g_qs.rem[r];
        unsigned cum = 0, bin = 0;
        for (int i = 0; i < 64; i++) {
            unsigned c = g_h3[r * 64 + i];
            if (rank >= cum && rank < cum + c) bin = (unsigned)i;
            cum += c;
        }
        sv[r] = __uint_as_float((g_qs.pref2[r] << 6) | bin);
    }
    __syncthreads();
    if (r == 0) {
        float q25 = sv[0] + 0.75f * (sv[1] - sv[0]);
        float q75 = sv[2] + 0.25f * (sv[3] - sv[2]);
        float iqr = q75 - q25;
        if (iqr < 1e-5f) iqr = 0.05f;
        g_qs.q25 = q25; g_qs.q75 = q75; g_qs.iqr = iqr;
    }
}

// ---------------------------------------------------------------------------
// Per-(b,c) sum / sumsq of x
// ---------------------------------------------------------------------------
__global__ void xstats_k(const float* __restrict__ x) {
    const int bc = blockIdx.x;
    const int sl = blockIdx.y;
    const float* p = x + ((size_t)bc << 18) + (size_t)sl * 32768;
    float s = 0.f, s2 = 0.f;
    for (int i = threadIdx.x; i < 32768; i += 256) {
        float v = p[i];
        s += v;
        s2 = fmaf(v, v, s2);
    }
#pragma unroll
    for (int o = 16; o; o >>= 1) {
        s  += __shfl_xor_sync(0xffffffffu, s, o);
        s2 += __shfl_xor_sync(0xffffffffu, s2, o);
    }
    __shared__ float ss[8], ss2[8];
    int w = threadIdx.x >> 5, l = threadIdx.x & 31;
    if (l == 0) { ss[w] = s; ss2[w] = s2; }
    __syncthreads();
    if (threadIdx.x == 0) {
        float a = 0.f, a2 = 0.f;
        for (int i = 0; i < 8; i++) { a += ss[i]; a2 += ss2[i]; }
        atomicAdd(&g_stats[bc].x, a);
        atomicAdd(&g_stats[bc].y, a2);
    }
}

// ---------------------------------------------------------------------------
// Adaptive thresholds (1 warp)
// ---------------------------------------------------------------------------
__global__ void thr_k(const float* __restrict__ chw) {
    const int t = threadIdx.x;
    const int c = t & 3;
    float w0 = chw[0], w1 = chw[1], w2 = chw[2], w3 = chw[3];
    float mx = fmaxf(fmaxf(w0, w1), fmaxf(w2, w3));
    float e0 = expf(w0 - mx), e1 = expf(w1 - mx), e2 = expf(w2 - mx), e3 = expf(w3 - mx);
    float se = e0 + e1 + e2 + e3;
    float cw = ((c == 0) ? e0 : (c == 1) ? e1 : (c == 2) ? e2 : e3) / se;

    float2 st = g_stats[t];
    const float N = (float)PLANE;
    float var = (st.y - st.x * st.x / N) / (N - 1.f);
    float gstd = sqrtf(fmaxf(var, 0.f));

    float q25 = g_qs.q25, q75 = g_qs.q75, iqr = g_qs.iqr;
    float lower = q25 - 0.5f * iqr;
    float upper = q75 + 0.5f * iqr;
    float gf = fminf(fmaxf(gstd * 5.f, 0.5f), 2.f);
    lower *= gf; upper *= gf;
    float cf = fminf(fmaxf(cw * gstd * 2.f, 0.8f), 1.2f);
    lower *= cf; upper *= cf;

    float d = fabsf(upper - lower);
#pragma unroll
    for (int o = 16; o; o >>= 1) d = fminf(d, __shfl_xor_sync(0xffffffffu, d, o));
    if (d < 1e-5f) {
        float mt = 0.5f * (upper + lower);
        lower = mt - 0.05f;
        upper = mt + 0.05f;
    }
    g_thr[t]      = lower;
    g_thr[32 + t] = fmaxf(upper - lower, 1e-5f);
}

// ---------------------------------------------------------------------------
// Final texture mask
// ---------------------------------------------------------------------------
__global__ void mask_k(float* __restrict__ out) {
    for (size_t i = (size_t)blockIdx.x * blockDim.x + threadIdx.x; i < (size_t)NPIX;
         i += (size_t)gridDim.x * blockDim.x) {
        int b = (int)(i >> 18);
        float v = g_fused[i];
        float acc = 0.f;
#pragma unroll
        for (int c = 0; c < 4; c++) {
            float lo  = g_thr[b * 4 + c];
            float dif = g_thr[32 + b * 4 + c];
            float nrm = fminf(fmaxf((v - lo) / dif, 0.f), 1.f);
            acc += 1.f / (1.f + expf(3.f - 6.f * nrm));
        }
        out[i] = 0.25f * acc;
    }
}

// ---------------------------------------------------------------------------
// Launch
// ---------------------------------------------------------------------------
extern "C" void kernel_launch(void* const* d_in, const int* in_sizes, int n_in,
                              void* d_out, int out_size) {
    const float* x        = (const float*)d_in[0];
    const float* conv1_w  = (const float*)d_in[1];
    const float* conv1_b  = (const float*)d_in[2];
    const float* conv2_w  = (const float*)d_in[3];
    const float* conv2_b  = (const float*)d_in[4];
    const float* conv3_w  = (const float*)d_in[5];
    const float* conv3_b  = (const float*)d_in[6];
    const float* fusion_w = (const float*)d_in[7];
    const float* fusion_b = (const float*)d_in[8];
    const float* chw      = (const float*)d_in[9];
    float* out = (float*)d_out;

    float* f1; cudaGetSymbolAddress((void**)&f1, g_f1);
    float* f2; cudaGetSymbolAddress((void**)&f2, g_f2);
    float* f ; cudaGetSymbolAddress((void**)&f , g_f);

    // dynamic shared sizes
    const int smem1 = (2 * 36 * 33 + 4 * 10 * 68) * 4;          // 20384
    const int smem2 = (2 * 288 * 17 + 8 * 18 * 68) * 4;         // 78336
    const int smem3 = (2 * 144 * 9 + 8 * 18 * 68) * 4;          // 49536
    cudaFuncSetAttribute(conv1_mma_k, cudaFuncAttributeMaxDynamicSharedMemorySize, smem1);
    cudaFuncSetAttribute(convB_mma_k<32, 16, true>, cudaFuncAttributeMaxDynamicSharedMemorySize, smem2);
    cudaFuncSetAttribute(convB_mma_k<16, 8, false>, cudaFuncAttributeMaxDynamicSharedMemorySize, smem3);

    zero_k<<<64, 256>>>();

    conv1_mma_k<<<dim3(W/64, H/8, B), 256, smem1>>>(x, conv1_w, conv1_b, f1);
    convB_mma_k<32, 16, true><<<dim3(W/64, H/16, B), 256, smem2>>>(f1, conv2_w, conv2_b, f2);
    convB_mma_k<16, 8, false><<<dim3(W/64, H/16, B), 256, smem3>>>(f2, conv3_w, conv3_b, f);

    boxstd_k<<<dim3(H/64, 3, B), 512>>>();

    fuse_hist1_k<<<192, 256>>>(fusion_w, fusion_b);
    scan1_k<<<1, 256>>>();
    hist2_k<<<dim3(64, 4), 256>>>();
    scan2_k<<<1, 256>>>();
    hist3_k<<<dim3(64, 4), 256>>>();
    scan3_k<<<1, 32>>>();

    xstats_k<<<dim3(32, 8), 256>>>(x);
    thr_k<<<1, 32>>>(chw);

    mask_k<<<1024, 256>>>(out);
}